// round 5
// baseline (speedup 1.0000x reference)
#include <cuda_runtime.h>
#include <cstdint>

#define SEQ 4096
#define HID 256
#define EMB 256

// ---------------------------------------------------------------------------
// Scratch: x_proj[t][j] (4096 x 256 fp32 = 4 MB). Device global (no alloc).
// ---------------------------------------------------------------------------
__device__ float g_xproj[SEQ * HID];

// ---------------------------------------------------------------------------
// Phase 1: x_proj = embedding[tokens] @ wx_w.T + wx_b  (~25us)
// ---------------------------------------------------------------------------
#define TOK_PER_BLK 16

__global__ __launch_bounds__(256) void xproj_kernel(
    const int* __restrict__ tokens,
    const float* __restrict__ embedding,
    const float* __restrict__ wx_w,
    const float* __restrict__ wx_b)
{
    __shared__ float emb_sm[TOK_PER_BLK * EMB];
    const int tid = threadIdx.x;
    const int t0  = blockIdx.x * TOK_PER_BLK;

    #pragma unroll
    for (int i = 0; i < TOK_PER_BLK; i++) {
        long tok = (long)tokens[t0 + i];
        emb_sm[i * EMB + tid] = embedding[tok * (long)EMB + tid];
    }
    __syncthreads();

    float acc[TOK_PER_BLK];
    #pragma unroll
    for (int i = 0; i < TOK_PER_BLK; i++) acc[i] = 0.f;

    const float4* wrow = reinterpret_cast<const float4*>(wx_w + tid * EMB);
    #pragma unroll 4
    for (int k4 = 0; k4 < EMB / 4; k4++) {
        float4 w = wrow[k4];
        #pragma unroll
        for (int i = 0; i < TOK_PER_BLK; i++) {
            float4 e = *reinterpret_cast<const float4*>(&emb_sm[i * EMB + 4 * k4]);
            acc[i] += w.x * e.x + w.y * e.y + w.z * e.z + w.w * e.w;
        }
    }

    const float b = wx_b[tid];
    #pragma unroll
    for (int i = 0; i < TOK_PER_BLK; i++)
        g_xproj[(t0 + i) * HID + tid] = acc[i] + b;
}

// ---------------------------------------------------------------------------
// Phase 2: serial recurrence, 2-CTA cluster — PARTIAL-SUM exchange.
//
// CTA r owns outputs (= h components) [r*128, r*128+128). Its k-range for any
// dot product is exactly the h-half it computes locally, so h NEVER crosses
// the cluster: instead each CTA computes partials for ALL 256 outputs over
// its local k-half, ships the 512 peer-destined partials (4 segs x 128
// outputs, unreduced, shipped IMMEDIATELY after stage-1 FMAs), and overlaps
// the ~215-cyc DSMEM flight with its own outputs' stage-2 FMAs.
//
// Thread map (512 thr): o = tid>>2, seg = tid&3. Each thread holds 32+32
// packed f32x2 weights (peer-output row + own-output row, same k chunk) and
// loads its 32 h values ONCE per step, reusing them for both stages.
//
// Inbox: inbox[2][512] uint, sentinel 0xFFFFFFFF (all-ones NaN; unreachable
// by finite arithmetic; integer compare is fast-math-proof). Writer (seg==0)
// polls its 4 words, sums, re-arms. Slot b consumed+re-armed at step t is
// next written by the peer at step t+2, causally after the re-arm through
// the step-t+1 data dependence + syncthreads chain (same distance-2 protocol
// that passed in R3).
//
// One __syncthreads per step: h double-buffered (local-only), writers store
// h[nxt] while others still read h[cur]; the end-of-step sync publishes it.
// ---------------------------------------------------------------------------
#define NCTA 2
#define THREADS2 512
#define OPC 128          // outputs per CTA
#define KSEG 32          // k's per thread
#define CH 36            // padded chunk stride (floats): seg*36 -> distinct banks
#define HALFP (4 * CH)   // 144 floats per h slot
#define SENTB 0xFFFFFFFFu

__device__ __forceinline__ uint32_t smem_u32(const void* p) {
    uint32_t a;
    asm("{ .reg .u64 t; cvta.to.shared.u64 t, %1; cvt.u32.u64 %0, t; }"
        : "=r"(a) : "l"(p));
    return a;
}
__device__ __forceinline__ uint32_t mapa_peer(uint32_t a, uint32_t rank) {
    uint32_t r;
    asm("mapa.shared::cluster.u32 %0, %1, %2;" : "=r"(r) : "r"(a), "r"(rank));
    return r;
}
__device__ __forceinline__ void st_remote_f32(uint32_t a, float v) {
    asm volatile("st.shared::cluster.f32 [%0], %1;" :: "r"(a), "f"(v) : "memory");
}
__device__ __forceinline__ void fma2(unsigned long long& acc,
                                     unsigned long long a, unsigned long long b) {
    asm("fma.rn.f32x2 %0, %1, %2, %0;" : "+l"(acc) : "l"(a), "l"(b));
}
__device__ __forceinline__ unsigned long long pack2(float x, float y) {
    unsigned long long v;
    asm("mov.b64 %0, {%1, %2};" : "=l"(v) : "f"(x), "f"(y));
    return v;
}
__device__ __forceinline__ void unpack2(unsigned long long v, float& x, float& y) {
    asm("mov.b64 {%0, %1}, %2;" : "=f"(x), "=f"(y) : "l"(v));
}

__global__ __launch_bounds__(THREADS2, 1) __cluster_dims__(NCTA, 1, 1)
void rnn_kernel(const float* __restrict__ wh_w,
                const float* __restrict__ wh_b,
                float* __restrict__ out)
{
    __shared__ __align__(16) float    hbuf[2][HALFP];     // local h half only
    __shared__ __align__(16) unsigned inbox[2][THREADS2]; // peer partials

    const int tid = threadIdx.x;
    uint32_t rank; asm("mov.u32 %0, %%cluster_ctarank;" : "=r"(rank));
    const uint32_t peer = rank ^ 1u;

    const int o     = tid >> 2;                 // output index within a CTA
    const int seg   = tid & 3;                  // k sub-chunk
    const int oglob = (int)rank * OPC + o;      // my output (stage 2)
    const int pglob = (int)peer * OPC + o;      // peer's output (stage 1)
    const bool writer = (seg == 0);

    // Weights (both rows restricted to MY k-range = rank*128 + seg*32 ..+32)
    unsigned long long wp[KSEG / 2], wo[KSEG / 2];
    {
        const int kbase = (int)rank * OPC + seg * KSEG;
        const float* rowP = wh_w + pglob * HID + kbase;
        const float* rowO = wh_w + oglob * HID + kbase;
        #pragma unroll
        for (int i = 0; i < KSEG / 2; i++) {
            wp[i] = pack2(rowP[2 * i], rowP[2 * i + 1]);
            wo[i] = pack2(rowO[2 * i], rowO[2 * i + 1]);
        }
    }

    // Init: h0 = 0; both inbox slots armed with sentinel.
    for (int i = tid; i < HALFP; i += THREADS2) hbuf[0][i] = 0.f;
    inbox[0][tid] = SENTB;
    inbox[1][tid] = SENTB;

    float bias = 0.f, xp_cur = 0.f, hn = 0.f;
    if (writer) {
        bias   = wh_b[oglob];
        xp_cur = g_xproj[oglob];
    }
    __syncthreads();
    // One-time: peer's inbox sentinels visible before any remote store.
    asm volatile("barrier.cluster.arrive.aligned;" ::: "memory");
    asm volatile("barrier.cluster.wait.aligned;"   ::: "memory");

    const uint32_t inbox_peer = mapa_peer(smem_u32(&inbox[0][0]), peer);
    const int wpos = (o >> 5) * CH + (o & 31);  // padded h slot for output o

    for (int t = 0; t < SEQ; t++) {
        const int cur = t & 1;
        const int nxt = cur ^ 1;

        float xp_next = 0.f;
        if (writer && (t + 1 < SEQ))
            xp_next = __ldg(&g_xproj[(t + 1) * HID + oglob]);

        // ---- load my 32 h values once (reused by both stages) ----
        const ulonglong2* h2 =
            reinterpret_cast<const ulonglong2*>(&hbuf[cur][seg * CH]);
        ulonglong2 h0 = h2[0], h1 = h2[1], h2v = h2[2], h3 = h2[3];
        ulonglong2 h4 = h2[4], h5 = h2[5], h6  = h2[6], h7 = h2[7];

        // ---- stage 1: partial for PEER output pglob; ship immediately ----
        {
            unsigned long long a0 = 0ull, a1 = 0ull;
            fma2(a0, wp[0],  h0.x);  fma2(a1, wp[1],  h0.y);
            fma2(a0, wp[2],  h1.x);  fma2(a1, wp[3],  h1.y);
            fma2(a0, wp[4],  h2v.x); fma2(a1, wp[5],  h2v.y);
            fma2(a0, wp[6],  h3.x);  fma2(a1, wp[7],  h3.y);
            fma2(a0, wp[8],  h4.x);  fma2(a1, wp[9],  h4.y);
            fma2(a0, wp[10], h5.x);  fma2(a1, wp[11], h5.y);
            fma2(a0, wp[12], h6.x);  fma2(a1, wp[13], h6.y);
            fma2(a0, wp[14], h7.x);  fma2(a1, wp[15], h7.y);
            float x0, y0, x1, y1;
            unpack2(a0, x0, y0); unpack2(a1, x1, y1);
            float s1 = (x0 + y0) + (x1 + y1);
            // entry index in peer inbox = o*4 + seg = tid (no pre-ship shuffle)
            st_remote_f32(inbox_peer + (uint32_t)(cur * THREADS2 + tid) * 4u, s1);
        }

        // ---- stage 2: partial for MY output (overlaps DSMEM flight) ----
        unsigned long long b0 = 0ull, b1 = 0ull;
        fma2(b0, wo[0],  h0.x);  fma2(b1, wo[1],  h0.y);
        fma2(b0, wo[2],  h1.x);  fma2(b1, wo[3],  h1.y);
        fma2(b0, wo[4],  h2v.x); fma2(b1, wo[5],  h2v.y);
        fma2(b0, wo[6],  h3.x);  fma2(b1, wo[7],  h3.y);
        fma2(b0, wo[8],  h4.x);  fma2(b1, wo[9],  h4.y);
        fma2(b0, wo[10], h5.x);  fma2(b1, wo[11], h5.y);
        fma2(b0, wo[12], h6.x);  fma2(b1, wo[13], h6.y);
        fma2(b0, wo[14], h7.x);  fma2(b1, wo[15], h7.y);
        float x0, y0, x1, y1;
        unpack2(b0, x0, y0); unpack2(b1, x1, y1);
        float s2 = (x0 + y0) + (x1 + y1);
        s2 += __shfl_xor_sync(0xFFFFFFFFu, s2, 1);
        s2 += __shfl_xor_sync(0xFFFFFFFFu, s2, 2);

        // ---- writer: poll peer partials, combine, sigmoid, store h ----
        if (writer) {
            volatile unsigned* p = &inbox[cur][o * 4];   // o*4 == tid here
            unsigned u0 = p[0]; while (u0 == SENTB) u0 = p[0];
            unsigned u1 = p[1]; while (u1 == SENTB) u1 = p[1];
            unsigned u2 = p[2]; while (u2 == SENTB) u2 = p[2];
            unsigned u3 = p[3]; while (u3 == SENTB) u3 = p[3];
            p[0] = SENTB; p[1] = SENTB; p[2] = SENTB; p[3] = SENTB;
            float v = (__uint_as_float(u0) + __uint_as_float(u1)) +
                      (__uint_as_float(u2) + __uint_as_float(u3));
            float z = s2 + v + bias + xp_cur;
            hn = __fdividef(1.f, 1.f + __expf(-z));
            hbuf[nxt][wpos] = hn;
            xp_cur = xp_next;
        }
        __syncthreads();   // publish hbuf[nxt]; all reads of hbuf[cur] done
    }

    if (writer) out[oglob] = hn;
}

// ---------------------------------------------------------------------------
// kernel_launch
//   d_in: [0] tokens i32[4096], [1] embedding f32[128000*256],
//         [2] wx_w f32[256*256], [3] wx_b f32[256],
//         [4] wh_w f32[256*256], [5] wh_b f32[256]
// ---------------------------------------------------------------------------
extern "C" void kernel_launch(void* const* d_in, const int* in_sizes, int n_in,
                              void* d_out, int out_size)
{
    const int*   tokens    = (const int*)d_in[0];
    const float* embedding = (const float*)d_in[1];
    const float* wx_w      = (const float*)d_in[2];
    const float* wx_b      = (const float*)d_in[3];
    const float* wh_w      = (const float*)d_in[4];
    const float* wh_b      = (const float*)d_in[5];
    float*       out       = (float*)d_out;

    xproj_kernel<<<SEQ / TOK_PER_BLK, 256>>>(tokens, embedding, wx_w, wx_b);
    rnn_kernel<<<NCTA, THREADS2>>>(wh_w, wh_b, out);
}